// round 12
// baseline (speedup 1.0000x reference)
#include <cuda_runtime.h>
#include <cuda_bf16.h>
#include <cstdint>

// Problem constants (fixed shapes from reference)
#define T_STEPS 32768
#define D_IN    1024
#define U_HID   1024
#define NG      4096   // 4*U

#define N_LSTM_CTAS 128
#define ROW_TILES   256   // 32768 / 128
#define COL_TILES   32    // 4096 / 128
#define N_TILES     (ROW_TILES * COL_TILES)

// ---------------- static device scratch (no allocs allowed) ----------------
__device__ float              g_zx[(size_t)T_STEPS * NG];  // x@kernel + bias (row-major by t)
// packed hidden state: lo32 = h bits, hi32 = step tag. Double-buffered by parity.
__device__ unsigned long long g_hpk[2][U_HID];
__device__ unsigned           g_rowready[ROW_TILES];       // per-row-tile completion counters

// ============================================================================
// State init (runs every launch: graph replays reuse device globals)
// ============================================================================
__global__ void init_state() {
    const int i = threadIdx.x;
    if (i < U_HID) {
        g_hpk[0][i] = 0ull;                   // h=0, tag=0 -> step 0 matches instantly
        g_hpk[1][i] = 0x8000000000000000ull;  // tag never matches a real step
    }
    if (i < ROW_TILES) g_rowready[i] = 0u;
}

// ============================================================================
// MEGA-KERNEL: CTAs 0..127 = persistent LSTM recurrence (R10 proven form);
// CTAs 128.. = GEMM producers. Producer uses f32x2 packed math with a
// register-lean single-buffered structure (must fit the 64-reg cap that
// __launch_bounds__(1024,1) imposes — R11's spill lesson).
// ============================================================================
#define GBM 128
#define GBN 128
#define GBK 16

__global__ __launch_bounds__(1024, 1) void mega(
    const float* __restrict__ x,     // [T, D]
    const float* __restrict__ kw,    // [D, 4U]
    const float* __restrict__ bias,  // [4U]
    const float* __restrict__ Rw,    // [U, 4U]
    float* __restrict__ out,         // [T, U]
    int nGemm)
{
    // ---- shared memory (union by role: each CTA touches only its own set) ----
    __shared__ float As[GBK][GBM + 4];
    __shared__ __align__(16) float Bs[GBK][GBN];
    __shared__ __align__(16) float sh_h[U_HID];
    __shared__ float sp[2][32 * 33];
    __shared__ float zs[32];

    const int tid = threadIdx.x;

    // ========================== GEMM producer role ==========================
    if (blockIdx.x >= N_LSTM_CTAS) {
        const int rank = blockIdx.x - N_LSTM_CTAS;

        // loaders
        const int aRow = tid >> 3;          // 0..127
        const int ac2  = (tid & 7) * 2;     // 0,2,..,14
        const int bRow = tid >> 6;          // 0..15
        const int bc2  = (tid & 63) * 2;    // 0,2,..,126
        // compute mapping: 2 rows x 8 cols per thread
        const int tx   = tid & 15;          // col octet: cols tx*8 .. tx*8+7
        const int ty   = tid >> 4;          // row pair:  rows ty*2, ty*2+1

        for (int tt = rank; tt < N_TILES; tt += nGemm) {
            const int rowT = tt >> 5;       // row-tile-major => rows ready ascending
            const int colT = tt & 31;
            const int cRow = rowT * GBM;
            const int cCol = colT * GBN;
            const float* Ap = x  + (size_t)cRow * D_IN;
            const float* Bp = kw + cCol;

            // 2 rows x 4 col-pairs of f32x2 accumulators (16 regs)
            unsigned long long acc0[4], acc1[4];
#pragma unroll
            for (int j = 0; j < 4; ++j) { acc0[j] = 0ull; acc1[j] = 0ull; }

            for (int kt = 0; kt < D_IN / GBK; ++kt) {
                // global loads (issued before the barrier to overlap latency)
                float2 ra = *(const float2*)&Ap[(size_t)aRow * D_IN + kt * GBK + ac2];
                float2 rb = *(const float2*)&Bp[(size_t)(kt * GBK + bRow) * NG + bc2];
                __syncthreads();   // previous iteration's smem reads complete
                As[ac2][aRow]     = ra.x;
                As[ac2 + 1][aRow] = ra.y;
                *(float2*)&Bs[bRow][bc2] = rb;
                __syncthreads();   // tile staged

#pragma unroll
                for (int k = 0; k < GBK; ++k) {
                    // A: two rows, packed broadcast {a,a} (2 movs)
                    float2 av = *(const float2*)&As[k][ty * 2];
                    unsigned long long ax, ay;
                    asm("mov.b64 %0, {%1, %1};" : "=l"(ax) : "f"(av.x));
                    asm("mov.b64 %0, {%1, %1};" : "=l"(ay) : "f"(av.y));
                    // B: 8 cols = 2 LDS.128, each yielding 2 aligned u64 pairs
                    const ulonglong2* bp =
                        reinterpret_cast<const ulonglong2*>(&Bs[k][tx * 8]);
                    ulonglong2 bv0 = bp[0];
                    ulonglong2 bv1 = bp[1];
                    asm("fma.rn.f32x2 %0, %1, %2, %3;"
                        : "=l"(acc0[0]) : "l"(ax), "l"(bv0.x), "l"(acc0[0]));
                    asm("fma.rn.f32x2 %0, %1, %2, %3;"
                        : "=l"(acc0[1]) : "l"(ax), "l"(bv0.y), "l"(acc0[1]));
                    asm("fma.rn.f32x2 %0, %1, %2, %3;"
                        : "=l"(acc0[2]) : "l"(ax), "l"(bv1.x), "l"(acc0[2]));
                    asm("fma.rn.f32x2 %0, %1, %2, %3;"
                        : "=l"(acc0[3]) : "l"(ax), "l"(bv1.y), "l"(acc0[3]));
                    asm("fma.rn.f32x2 %0, %1, %2, %3;"
                        : "=l"(acc1[0]) : "l"(ay), "l"(bv0.x), "l"(acc1[0]));
                    asm("fma.rn.f32x2 %0, %1, %2, %3;"
                        : "=l"(acc1[1]) : "l"(ay), "l"(bv0.y), "l"(acc1[1]));
                    asm("fma.rn.f32x2 %0, %1, %2, %3;"
                        : "=l"(acc1[2]) : "l"(ay), "l"(bv1.x), "l"(acc1[2]));
                    asm("fma.rn.f32x2 %0, %1, %2, %3;"
                        : "=l"(acc1[3]) : "l"(ay), "l"(bv1.y), "l"(acc1[3]));
                }
            }

            // epilogue: + bias (packed), two coalesced rows of 32B stores
            {
                const ulonglong2* bi =
                    reinterpret_cast<const ulonglong2*>(&bias[cCol + tx * 8]);
                ulonglong2 bi0 = bi[0];
                ulonglong2 bi1 = bi[1];
#pragma unroll
                for (int j = 0; j < 4; ++j) {
                    const unsigned long long bb = (j == 0) ? bi0.x : (j == 1) ? bi0.y
                                                : (j == 2) ? bi1.x : bi1.y;
                    asm("add.rn.f32x2 %0, %1, %2;"
                        : "=l"(acc0[j]) : "l"(acc0[j]), "l"(bb));
                    asm("add.rn.f32x2 %0, %1, %2;"
                        : "=l"(acc1[j]) : "l"(acc1[j]), "l"(bb));
                }
                const int r0 = cRow + ty * 2;
                ulonglong2* d0 = reinterpret_cast<ulonglong2*>(
                    &g_zx[(size_t)r0 * NG + cCol + tx * 8]);
                ulonglong2* d1 = reinterpret_cast<ulonglong2*>(
                    &g_zx[(size_t)(r0 + 1) * NG + cCol + tx * 8]);
                d0[0] = make_ulonglong2(acc0[0], acc0[1]);
                d0[1] = make_ulonglong2(acc0[2], acc0[3]);
                d1[0] = make_ulonglong2(acc1[0], acc1[1]);
                d1[1] = make_ulonglong2(acc1[2], acc1[3]);
            }
            __syncthreads();          // all stores of this tile issued
            if (tid == 0) {
                __threadfence();      // gpu-scope: make tile stores visible
                asm volatile("red.release.gpu.global.add.u32 [%0], %1;"
                             :: "l"(&g_rowready[rowT]), "r"(1u) : "memory");
            }
            __syncthreads();
        }
        return;
    }

    // ========================== LSTM recurrence role ==========================
    const int w   = tid >> 5;
    const int l   = tid & 31;
    const int u0  = blockIdx.x * 8;
    // stage-1 column for lane l; stage-2 column for warp w
    const int col  = ((l >> 3) << 10) + u0 + (l & 7);
    const int col2 = ((w >> 3) << 10) + u0 + (w & 7);

    // packed weight pairs: W2[m] = {R[32w+2m][col], R[32w+2m+1][col]}
    unsigned long long W2[16];
    {
        const float* wp = Rw + ((size_t)(w << 5)) * NG + col;
#pragma unroll
        for (int m = 0; m < 16; ++m) {
            float w0 = wp[(size_t)(2 * m) * NG];
            float w1 = wp[(size_t)(2 * m + 1) * NG];
            asm("mov.b64 %0, {%1, %2};" : "=l"(W2[m]) : "f"(w0), "f"(w1));
        }
    }

    float cst = 0.f;                       // cell state (warp 0, lanes 0..7)
    const float* zxp = g_zx + col2;

    // zx readiness tracking (only l==0 lanes use it)
    int zreadyT = 0;
    auto wait_tile = [&](int tile) {
        unsigned v;
        do {
            asm volatile("ld.acquire.gpu.global.u32 %0, [%1];"
                         : "=r"(v) : "l"(&g_rowready[tile]) : "memory");
        } while (v < (unsigned)COL_TILES);
    };

    float zxv = 0.f;
    if (l == 0) {               // initial zx (row 0) — wait for tile 0
        wait_tile(0);
        zreadyT = 1;
        zxv = __ldg(zxp);
    }

    const int e  = (w << 5) + l;           // element this lane polls
    const int jj = l & 7;

    for (int t = 0; t < T_STEPS; ++t) {
        // prefetch next step's zx early (gated by tile readiness)
        float zxn = 0.f;
        if (l == 0 && t + 1 < T_STEPS) {
            const int tl = (t + 1) >> 7;
            if (tl >= zreadyT) { wait_tile(tl); zreadyT = tl + 1; }
            zxn = __ldg(&zxp[(size_t)(t + 1) * NG]);
        }

        // poll the packed {h, tag} word; tag==t => h is the step-t value
        {
            const unsigned long long* src = &g_hpk[t & 1][e];
            unsigned long long pk;
            do {
                asm volatile("ld.volatile.global.u64 %0, [%1];"
                             : "=l"(pk) : "l"(src));
            } while ((unsigned)(pk >> 32) != (unsigned)t);
            sh_h[e] = __uint_as_float((unsigned)pk);
        }
        __syncwarp();

        float* const spb = sp[t & 1];      // step-parity buffer

        // stage 1: packed-f32x2 partial dot over rows [32w,32w+32) for `col`
        unsigned long long acc0 = 0ull, acc1 = 0ull;
        const ulonglong2* h2 = reinterpret_cast<const ulonglong2*>(sh_h + (w << 5));
#pragma unroll
        for (int k = 0; k < 8; ++k) {
            ulonglong2 hv = h2[k];  // all lanes same address -> smem broadcast
            asm("fma.rn.f32x2 %0, %1, %2, %3;"
                : "=l"(acc0) : "l"(hv.x), "l"(W2[2 * k]),     "l"(acc0));
            asm("fma.rn.f32x2 %0, %1, %2, %3;"
                : "=l"(acc1) : "l"(hv.y), "l"(W2[2 * k + 1]), "l"(acc1));
        }
        float a0, a1, b0, b1;
        asm("mov.b64 {%0, %1}, %2;" : "=f"(a0), "=f"(a1) : "l"(acc0));
        asm("mov.b64 {%0, %1}, %2;" : "=f"(b0), "=f"(b1) : "l"(acc1));
        spb[l * 33 + w] = (a0 + b0) + (a1 + b1);
        __syncthreads();  // bar A: all partials in sp

        // stage 2: warp w reduces its column; 4 partials/lane then 3 shfls;
        // lane 0 applies the activation (parallel across warps)
        {
            const float* spc = spb + w * 33 + jj;
            float s = (spc[0] + spc[8]) + (spc[16] + spc[24]);
            s += __shfl_xor_sync(0xffffffffu, s, 4);
            s += __shfl_xor_sync(0xffffffffu, s, 2);
            s += __shfl_xor_sync(0xffffffffu, s, 1);
            if (l == 0) {
                const float z = s + zxv;
                const int   q = w >> 3;
                if (q == 2) {               // g gate: tanh
                    const float zc = fminf(fmaxf(z, -15.f), 15.f);
                    const float ee = __expf(2.f * zc);
                    zs[w] = __fdividef(ee - 1.f, ee + 1.f);
                } else {                    // i,f,o gates: sigmoid
                    const float ee = __expf(-z);
                    zs[w] = __fdividef(1.f, 1.f + ee);
                }
            }
        }
        __syncthreads();  // bar B: activated gate values ready

        // final: warp 0, lanes 0..7 update cell and publish
        if (w == 0 && l < 8) {
            const float ig = zs[l],      fg = zs[8 + l];
            const float gg = zs[16 + l], og = zs[24 + l];
            const float c2 = fg * cst + ig * gg;
            cst = c2;
            const float cc = fminf(fmaxf(c2, -15.f), 15.f);
            const float ec = __expf(2.f * cc);
            const float h  = og * __fdividef(ec - 1.f, ec + 1.f);
            // publish FIRST: one coalesced 64B wavefront (8 lanes x 8B)
            unsigned long long pkw;
            asm("mov.b64 %0, {%1, %2};"
                : "=l"(pkw) : "f"(h), "r"((unsigned)(t + 1)));
            asm volatile("st.volatile.global.u64 [%0], %1;"
                         :: "l"(&g_hpk[(t + 1) & 1][u0 + l]), "l"(pkw)
                         : "memory");
            out[(size_t)t * U_HID + u0 + l] = h;    // off critical path
        }
        zxv = zxn;
        // no trailing barrier: zs(t+1) writes happen after bar A(t+1), which
        // warp 0 only reaches after gates; sp reuse is parity-buffered.
    }
}

// ============================================================================
extern "C" void kernel_launch(void* const* d_in, const int* in_sizes, int n_in,
                              void* d_out, int out_size) {
    const float* x    = (const float*)d_in[0];  // [1, 32768, 1024]
    const float* kw   = (const float*)d_in[1];  // [1024, 4096]
    const float* rw   = (const float*)d_in[2];  // [1024, 4096]
    const float* bias = (const float*)d_in[3];  // [4096]
    float* out = (float*)d_out;                 // [1, 32768, 1024]

    int sms = 148;
    cudaDeviceGetAttribute(&sms, cudaDevAttrMultiProcessorCount, 0);
    int nGemm = sms - N_LSTM_CTAS;              // producer CTAs on spare SMs
    if (nGemm < 1) nGemm = 1;

    init_state<<<1, 1024>>>();
    mega<<<N_LSTM_CTAS + nGemm, 1024>>>(x, kw, bias, rw, out, nGemm);
}

// round 14
// speedup vs baseline: 2.3028x; 2.3028x over previous
#include <cuda_runtime.h>
#include <cuda_bf16.h>
#include <cstdint>

// Problem constants (fixed shapes from reference)
#define T_STEPS 32768
#define D_IN    1024
#define U_HID   1024
#define NG      4096   // 4*U

#define N_LSTM_CTAS 128
#define ROW_TILES   256   // 32768 / 128
#define COL_TILES   32    // 4096 / 128
#define N_TILES     (ROW_TILES * COL_TILES)

// Prologue: LSTM CTAs pre-compute the first PRO_ROWS row-tiles themselves.
#define PRO_ROWS    32
#define PRO_TILES   (PRO_ROWS * COL_TILES)   // 1024 = 8 per LSTM CTA

// ---------------- static device scratch (no allocs allowed) ----------------
__device__ float              g_zx[(size_t)T_STEPS * NG];  // x@kernel + bias (row-major by t)
// packed hidden state: lo32 = h bits, hi32 = step tag. Double-buffered by parity.
__device__ unsigned long long g_hpk[2][U_HID];
__device__ unsigned           g_rowready[ROW_TILES];       // per-row-tile completion counters

// ============================================================================
// State init (runs every launch: graph replays reuse device globals)
// ============================================================================
__global__ void init_state() {
    const int i = threadIdx.x;
    if (i < U_HID) {
        g_hpk[0][i] = 0ull;                   // h=0, tag=0 -> step 0 matches instantly
        g_hpk[1][i] = 0x8000000000000000ull;  // tag never matches a real step
    }
    if (i < ROW_TILES) g_rowready[i] = 0u;
}

// ============================================================================
// One 128x128 zx tile: scalar 4x4 microtile GEMM (proven R9 form, ~120us),
// double-buffered smem, publishes completion via red.release on rowready.
// Called by BOTH producer CTAs and LSTM CTAs (prologue).
// ============================================================================
#define GBM 128
#define GBN 128
#define GBK 16

__device__ __forceinline__ void gemm_tile(
    const float* __restrict__ x, const float* __restrict__ kw,
    const float* __restrict__ bias, int tt, int tid,
    float (*As)[GBK][GBM + 4], float (*Bs)[GBK][GBN])
{
    const int aRow = tid >> 3;          // 0..127
    const int ac2  = (tid & 7) * 2;     // 0,2,..,14
    const int bRow = tid >> 6;          // 0..15
    const int bc2  = (tid & 63) * 2;    // 0,2,..,126
    const int tx   = tid & 31;          // col/4
    const int ty   = tid >> 5;          // row/4

    const int rowT = tt >> 5;
    const int colT = tt & 31;
    const int cRow = rowT * GBM;
    const int cCol = colT * GBN;
    const float* Ap = x  + (size_t)cRow * D_IN;
    const float* Bp = kw + cCol;

    float acc[4][4];
#pragma unroll
    for (int i = 0; i < 4; ++i)
#pragma unroll
        for (int j = 0; j < 4; ++j) acc[i][j] = 0.f;

    float2 ra, rb;
    auto loadG = [&](int kt) {
        ra = *(const float2*)&Ap[(size_t)aRow * D_IN + kt * GBK + ac2];
        rb = *(const float2*)&Bp[(size_t)(kt * GBK + bRow) * NG + bc2];
    };
    auto storeS = [&](int buf) {
        As[buf][ac2][aRow]     = ra.x;
        As[buf][ac2 + 1][aRow] = ra.y;
        *(float2*)&Bs[buf][bRow][bc2] = rb;
    };

    loadG(0);
    storeS(0);
    __syncthreads();

    const int nT = D_IN / GBK;  // 64
    for (int kt = 0; kt < nT; ++kt) {
        const int buf = kt & 1;
        if (kt + 1 < nT) loadG(kt + 1);
#pragma unroll
        for (int k = 0; k < GBK; ++k) {
            float4 av = *(const float4*)&As[buf][k][ty * 4];
            float4 bv = *(const float4*)&Bs[buf][k][tx * 4];
            float ar[4] = {av.x, av.y, av.z, av.w};
            float br[4] = {bv.x, bv.y, bv.z, bv.w};
#pragma unroll
            for (int i = 0; i < 4; ++i)
#pragma unroll
                for (int j = 0; j < 4; ++j)
                    acc[i][j] = fmaf(ar[i], br[j], acc[i][j]);
        }
        if (kt + 1 < nT) storeS(buf ^ 1);
        __syncthreads();
    }

    // epilogue: + bias, coalesced float4 stores, row-major by t
    float4 bb4 = *(const float4*)&bias[cCol + tx * 4];
    float bb[4] = {bb4.x, bb4.y, bb4.z, bb4.w};
#pragma unroll
    for (int i = 0; i < 4; ++i) {
        const int r = cRow + ty * 4 + i;
        float4 o = make_float4(acc[i][0] + bb[0], acc[i][1] + bb[1],
                               acc[i][2] + bb[2], acc[i][3] + bb[3]);
        *(float4*)&g_zx[(size_t)r * NG + cCol + tx * 4] = o;
    }
    __syncthreads();          // all stores of this tile issued
    if (tid == 0) {
        __threadfence();      // gpu-scope: make tile stores visible
        asm volatile("red.release.gpu.global.add.u32 [%0], %1;"
                     :: "l"(&g_rowready[rowT]), "r"(1u) : "memory");
    }
    __syncthreads();
}

// ============================================================================
// MEGA-KERNEL:
//   CTAs 0..127:  prologue GEMM (row-tiles 0..PRO_ROWS-1, 8 tiles each at full
//                 152-SM width, ~1ms) then persistent LSTM recurrence (R10
//                 proven form). The 32-row zx runway absorbs the producers'
//                 per-row deficit so they never pace the recurrence again.
//   CTAs 128..:   GEMM producers, row-tiles PRO_ROWS..255, row-major.
// ============================================================================
__global__ __launch_bounds__(1024, 1) void mega(
    const float* __restrict__ x,     // [T, D]
    const float* __restrict__ kw,    // [D, 4U]
    const float* __restrict__ bias,  // [4U]
    const float* __restrict__ Rw,    // [U, 4U]
    float* __restrict__ out,         // [T, U]
    int nGemm)
{
    // ---- shared memory (time-disjoint use per CTA role/phase) ----
    __shared__ float As[2][GBK][GBM + 4];
    __shared__ float Bs[2][GBK][GBN];
    __shared__ __align__(16) float sh_h[U_HID];
    __shared__ float sp[2][32 * 33];
    __shared__ float zs[32];

    const int tid = threadIdx.x;

    // ========================== GEMM producer role ==========================
    if (blockIdx.x >= N_LSTM_CTAS) {
        const int rank = blockIdx.x - N_LSTM_CTAS;
        for (int tt = PRO_TILES + rank; tt < N_TILES; tt += nGemm)
            gemm_tile(x, kw, bias, tt, tid, As, Bs);
        return;
    }

    // ==================== LSTM CTA: prologue GEMM phase =====================
    // CTA hr handles tiles {hr, hr+128, ..., hr+896} covering row-tiles 0..31.
    {
        const int hr = blockIdx.x;
#pragma unroll 1
        for (int i = 0; i < PRO_TILES / N_LSTM_CTAS; ++i)
            gemm_tile(x, kw, bias, hr + i * N_LSTM_CTAS, tid, As, Bs);
    }

    // ========================== LSTM recurrence role ==========================
    const int w   = tid >> 5;
    const int l   = tid & 31;
    const int u0  = blockIdx.x * 8;
    // stage-1 column for lane l; stage-2 column for warp w
    const int col  = ((l >> 3) << 10) + u0 + (l & 7);
    const int col2 = ((w >> 3) << 10) + u0 + (w & 7);

    // packed weight pairs: W2[m] = {R[32w+2m][col], R[32w+2m+1][col]}
    // (loaded AFTER the prologue so these 32 regs aren't live during GEMM)
    unsigned long long W2[16];
    {
        const float* wp = Rw + ((size_t)(w << 5)) * NG + col;
#pragma unroll
        for (int m = 0; m < 16; ++m) {
            float w0 = wp[(size_t)(2 * m) * NG];
            float w1 = wp[(size_t)(2 * m + 1) * NG];
            asm("mov.b64 %0, {%1, %2};" : "=l"(W2[m]) : "f"(w0), "f"(w1));
        }
    }

    float cst = 0.f;                       // cell state (warp 0, lanes 0..7)
    const float* zxp = g_zx + col2;

    // zx readiness tracking (only l==0 lanes use it)
    int zreadyT = 0;
    auto wait_tile = [&](int tile) {
        unsigned v;
        do {
            asm volatile("ld.acquire.gpu.global.u32 %0, [%1];"
                         : "=r"(v) : "l"(&g_rowready[tile]) : "memory");
        } while (v < (unsigned)COL_TILES);
    };

    float zxv = 0.f;
    if (l == 0) {               // initial zx (row 0) — produced by the prologue
        wait_tile(0);
        zreadyT = 1;
        zxv = __ldg(zxp);
    }

    const int e  = (w << 5) + l;           // element this lane polls
    const int jj = l & 7;

    for (int t = 0; t < T_STEPS; ++t) {
        // prefetch next step's zx early (gated by tile readiness)
        float zxn = 0.f;
        if (l == 0 && t + 1 < T_STEPS) {
            const int tl = (t + 1) >> 7;
            if (tl >= zreadyT) { wait_tile(tl); zreadyT = tl + 1; }
            zxn = __ldg(&zxp[(size_t)(t + 1) * NG]);
        }

        // poll the packed {h, tag} word; tag==t => h is the step-t value
        {
            const unsigned long long* src = &g_hpk[t & 1][e];
            unsigned long long pk;
            do {
                asm volatile("ld.volatile.global.u64 %0, [%1];"
                             : "=l"(pk) : "l"(src));
            } while ((unsigned)(pk >> 32) != (unsigned)t);
            sh_h[e] = __uint_as_float((unsigned)pk);
        }
        __syncwarp();

        float* const spb = sp[t & 1];      // step-parity buffer

        // stage 1: packed-f32x2 partial dot over rows [32w,32w+32) for `col`
        unsigned long long acc0 = 0ull, acc1 = 0ull;
        const ulonglong2* h2 = reinterpret_cast<const ulonglong2*>(sh_h + (w << 5));
#pragma unroll
        for (int k = 0; k < 8; ++k) {
            ulonglong2 hv = h2[k];  // all lanes same address -> smem broadcast
            asm("fma.rn.f32x2 %0, %1, %2, %3;"
                : "=l"(acc0) : "l"(hv.x), "l"(W2[2 * k]),     "l"(acc0));
            asm("fma.rn.f32x2 %0, %1, %2, %3;"
                : "=l"(acc1) : "l"(hv.y), "l"(W2[2 * k + 1]), "l"(acc1));
        }
        float a0, a1, b0, b1;
        asm("mov.b64 {%0, %1}, %2;" : "=f"(a0), "=f"(a1) : "l"(acc0));
        asm("mov.b64 {%0, %1}, %2;" : "=f"(b0), "=f"(b1) : "l"(acc1));
        spb[l * 33 + w] = (a0 + b0) + (a1 + b1);
        __syncthreads();  // bar A: all partials in sp

        // stage 2: warp w reduces its column; 4 partials/lane then 3 shfls;
        // lane 0 applies the activation (parallel across warps)
        {
            const float* spc = spb + w * 33 + jj;
            float s = (spc[0] + spc[8]) + (spc[16] + spc[24]);
            s += __shfl_xor_sync(0xffffffffu, s, 4);
            s += __shfl_xor_sync(0xffffffffu, s, 2);
            s += __shfl_xor_sync(0xffffffffu, s, 1);
            if (l == 0) {
                const float z = s + zxv;
                const int   q = w >> 3;
                if (q == 2) {               // g gate: tanh
                    const float zc = fminf(fmaxf(z, -15.f), 15.f);
                    const float ee = __expf(2.f * zc);
                    zs[w] = __fdividef(ee - 1.f, ee + 1.f);
                } else {                    // i,f,o gates: sigmoid
                    const float ee = __expf(-z);
                    zs[w] = __fdividef(1.f, 1.f + ee);
                }
            }
        }
        __syncthreads();  // bar B: activated gate values ready

        // final: warp 0, lanes 0..7 update cell and publish
        if (w == 0 && l < 8) {
            const float ig = zs[l],      fg = zs[8 + l];
            const float gg = zs[16 + l], og = zs[24 + l];
            const float c2 = fg * cst + ig * gg;
            cst = c2;
            const float cc = fminf(fmaxf(c2, -15.f), 15.f);
            const float ec = __expf(2.f * cc);
            const float h  = og * __fdividef(ec - 1.f, ec + 1.f);
            // publish FIRST: one coalesced 64B wavefront (8 lanes x 8B)
            unsigned long long pkw;
            asm("mov.b64 %0, {%1, %2};"
                : "=l"(pkw) : "f"(h), "r"((unsigned)(t + 1)));
            asm volatile("st.volatile.global.u64 [%0], %1;"
                         :: "l"(&g_hpk[(t + 1) & 1][u0 + l]), "l"(pkw)
                         : "memory");
            out[(size_t)t * U_HID + u0 + l] = h;    // off critical path
        }
        zxv = zxn;
        // no trailing barrier: zs(t+1) writes happen after bar A(t+1), which
        // warp 0 only reaches after gates; sp reuse is parity-buffered.
    }
}

// ============================================================================
extern "C" void kernel_launch(void* const* d_in, const int* in_sizes, int n_in,
                              void* d_out, int out_size) {
    const float* x    = (const float*)d_in[0];  // [1, 32768, 1024]
    const float* kw   = (const float*)d_in[1];  // [1024, 4096]
    const float* rw   = (const float*)d_in[2];  // [1024, 4096]
    const float* bias = (const float*)d_in[3];  // [4096]
    float* out = (float*)d_out;                 // [1, 32768, 1024]

    int sms = 148;
    cudaDeviceGetAttribute(&sms, cudaDevAttrMultiProcessorCount, 0);
    int nGemm = sms - N_LSTM_CTAS;              // producer CTAs on spare SMs
    if (nGemm < 1) nGemm = 1;

    init_state<<<1, 1024>>>();
    mega<<<N_LSTM_CTAS + nGemm, 1024>>>(x, kw, bias, rw, out, nGemm);
}

// round 15
// speedup vs baseline: 2.4953x; 1.0836x over previous
#include <cuda_runtime.h>
#include <cuda_bf16.h>
#include <cstdint>

// Problem constants (fixed shapes from reference)
#define T_STEPS 32768
#define D_IN    1024
#define U_HID   1024
#define NG      4096   // 4*U

#define N_LSTM_CTAS 128

// Producer tiles: 256 rows x 128 cols
#define GBM 256
#define GBN 128
#define GBK 16
#define ROW_GROUPS  128   // 32768 / 256
#define COL_TILES   32    // 4096 / 128
#define N_TILES     (ROW_GROUPS * COL_TILES)   // 4096

// ---------------- static device scratch (no allocs allowed) ----------------
__device__ float              g_zx[(size_t)T_STEPS * NG];  // x@kernel + bias (row-major by t)
// packed hidden state: lo32 = h bits, hi32 = step tag. Double-buffered by parity.
__device__ unsigned long long g_hpk[2][U_HID];
__device__ unsigned           g_rowready[ROW_GROUPS];      // per-256-row-group counters

// ============================================================================
// State init (runs every launch: graph replays reuse device globals)
// ============================================================================
__global__ void init_state() {
    const int i = threadIdx.x;
    if (i < U_HID) {
        g_hpk[0][i] = 0ull;                   // h=0, tag=0 -> step 0 matches instantly
        g_hpk[1][i] = 0x8000000000000000ull;  // tag never matches a real step
    }
    if (i < ROW_GROUPS) g_rowready[i] = 0u;
}

// ============================================================================
// MEGA-KERNEL: CTAs 0..127 = persistent LSTM recurrence (EXACT R10 proven
// form — untouched); CTAs 128.. = GEMM producers with an 8x4 microtile on
// 256x128 tiles (FMA-bound: ~2x the old producer rate), single-buffered smem
// to stay under the 64-reg cap.
// ============================================================================
__global__ __launch_bounds__(1024, 1) void mega(
    const float* __restrict__ x,     // [T, D]
    const float* __restrict__ kw,    // [D, 4U]
    const float* __restrict__ bias,  // [4U]
    const float* __restrict__ Rw,    // [U, 4U]
    float* __restrict__ out,         // [T, U]
    int nGemm)
{
    // ---- shared memory (union by role: each CTA touches only its own set) ----
    __shared__ float As[GBK][GBM + 4];            // 16 x 260 floats = 16.6 KB
    __shared__ __align__(16) float Bs[GBK][GBN];  // 8 KB
    __shared__ __align__(16) float sh_h[U_HID];
    __shared__ float sp[2][32 * 33];
    __shared__ float zs[32];

    const int tid = threadIdx.x;

    // ========================== GEMM producer role ==========================
    if (blockIdx.x >= N_LSTM_CTAS) {
        const int rank = blockIdx.x - N_LSTM_CTAS;

        // loaders: A 256x16 (one float4 along k per thread), B 16x128
        const int aRow = tid >> 2;          // 0..255
        const int ac4  = (tid & 3) * 4;     // 0,4,8,12
        const int bRow = tid >> 6;          // 0..15
        const int bc2  = (tid & 63) * 2;    // 0,2,..,126
        // compute mapping: 8 rows x 4 cols per thread
        const int tx   = tid & 31;          // cols tx*4 .. tx*4+3
        const int ty   = tid >> 5;          // rows ty*8 .. ty*8+7

        for (int tt = rank; tt < N_TILES; tt += nGemm) {
            const int rowT = tt >> 5;       // row-group-major => ready ascending
            const int colT = tt & 31;
            const int cRow = rowT * GBM;
            const int cCol = colT * GBN;
            const float* Ap = x  + (size_t)cRow * D_IN;
            const float* Bp = kw + cCol;

            float acc[8][4];
#pragma unroll
            for (int i = 0; i < 8; ++i)
#pragma unroll
                for (int j = 0; j < 4; ++j) acc[i][j] = 0.f;

            for (int kt = 0; kt < D_IN / GBK; ++kt) {
                // global loads (overlap: other warps still in prev FMA loop)
                float4 ra = *(const float4*)&Ap[(size_t)aRow * D_IN + kt * GBK + ac4];
                float2 rb = *(const float2*)&Bp[(size_t)(kt * GBK + bRow) * NG + bc2];
                __syncthreads();   // previous iteration's smem reads complete
                As[ac4 + 0][aRow] = ra.x;
                As[ac4 + 1][aRow] = ra.y;
                As[ac4 + 2][aRow] = ra.z;
                As[ac4 + 3][aRow] = ra.w;
                *(float2*)&Bs[bRow][bc2] = rb;
                __syncthreads();   // tile staged

#pragma unroll
                for (int k = 0; k < GBK; ++k) {
                    // A: 8 rows = 2 float4, warp-broadcast (all lanes same ty)
                    float4 a0 = *(const float4*)&As[k][ty * 8];
                    float4 a1 = *(const float4*)&As[k][ty * 8 + 4];
                    float4 bv = *(const float4*)&Bs[k][tx * 4];
                    float ar[8] = {a0.x, a0.y, a0.z, a0.w, a1.x, a1.y, a1.z, a1.w};
                    float br[4] = {bv.x, bv.y, bv.z, bv.w};
#pragma unroll
                    for (int i = 0; i < 8; ++i)
#pragma unroll
                        for (int j = 0; j < 4; ++j)
                            acc[i][j] = fmaf(ar[i], br[j], acc[i][j]);
                }
            }

            // epilogue: + bias, 8 coalesced float4 row-stores
            float4 bb4 = *(const float4*)&bias[cCol + tx * 4];
#pragma unroll
            for (int i = 0; i < 8; ++i) {
                const int r = cRow + ty * 8 + i;
                float4 o = make_float4(acc[i][0] + bb4.x, acc[i][1] + bb4.y,
                                       acc[i][2] + bb4.z, acc[i][3] + bb4.w);
                *(float4*)&g_zx[(size_t)r * NG + cCol + tx * 4] = o;
            }
            __syncthreads();          // all stores of this tile issued
            if (tid == 0) {
                __threadfence();      // gpu-scope: make tile stores visible
                asm volatile("red.release.gpu.global.add.u32 [%0], %1;"
                             :: "l"(&g_rowready[rowT]), "r"(1u) : "memory");
            }
            __syncthreads();
        }
        return;
    }

    // ========================== LSTM recurrence role ==========================
    const int w   = tid >> 5;
    const int l   = tid & 31;
    const int u0  = blockIdx.x * 8;
    // stage-1 column for lane l; stage-2 column for warp w
    const int col  = ((l >> 3) << 10) + u0 + (l & 7);
    const int col2 = ((w >> 3) << 10) + u0 + (w & 7);

    // packed weight pairs: W2[m] = {R[32w+2m][col], R[32w+2m+1][col]}
    unsigned long long W2[16];
    {
        const float* wp = Rw + ((size_t)(w << 5)) * NG + col;
#pragma unroll
        for (int m = 0; m < 16; ++m) {
            float w0 = wp[(size_t)(2 * m) * NG];
            float w1 = wp[(size_t)(2 * m + 1) * NG];
            asm("mov.b64 %0, {%1, %2};" : "=l"(W2[m]) : "f"(w0), "f"(w1));
        }
    }

    float cst = 0.f;                       // cell state (warp 0, lanes 0..7)
    const float* zxp = g_zx + col2;

    // zx readiness tracking (only l==0 lanes use it); 256 steps per group
    int zreadyT = 0;
    auto wait_tile = [&](int grp) {
        unsigned v;
        do {
            asm volatile("ld.acquire.gpu.global.u32 %0, [%1];"
                         : "=r"(v) : "l"(&g_rowready[grp]) : "memory");
        } while (v < (unsigned)COL_TILES);
    };

    float zxv = 0.f;
    if (l == 0) {               // initial zx (row 0) — wait for group 0
        wait_tile(0);
        zreadyT = 1;
        zxv = __ldg(zxp);
    }

    const int e  = (w << 5) + l;           // element this lane polls
    const int jj = l & 7;

    for (int t = 0; t < T_STEPS; ++t) {
        // prefetch next step's zx early (gated by group readiness)
        float zxn = 0.f;
        if (l == 0 && t + 1 < T_STEPS) {
            const int tl = (t + 1) >> 8;
            if (tl >= zreadyT) { wait_tile(tl); zreadyT = tl + 1; }
            zxn = __ldg(&zxp[(size_t)(t + 1) * NG]);
        }

        // poll the packed {h, tag} word; tag==t => h is the step-t value
        {
            const unsigned long long* src = &g_hpk[t & 1][e];
            unsigned long long pk;
            do {
                asm volatile("ld.volatile.global.u64 %0, [%1];"
                             : "=l"(pk) : "l"(src));
            } while ((unsigned)(pk >> 32) != (unsigned)t);
            sh_h[e] = __uint_as_float((unsigned)pk);
        }
        __syncwarp();

        float* const spb = sp[t & 1];      // step-parity buffer

        // stage 1: packed-f32x2 partial dot over rows [32w,32w+32) for `col`
        unsigned long long acc0 = 0ull, acc1 = 0ull;
        const ulonglong2* h2 = reinterpret_cast<const ulonglong2*>(sh_h + (w << 5));
#pragma unroll
        for (int k = 0; k < 8; ++k) {
            ulonglong2 hv = h2[k];  // all lanes same address -> smem broadcast
            asm("fma.rn.f32x2 %0, %1, %2, %3;"
                : "=l"(acc0) : "l"(hv.x), "l"(W2[2 * k]),     "l"(acc0));
            asm("fma.rn.f32x2 %0, %1, %2, %3;"
                : "=l"(acc1) : "l"(hv.y), "l"(W2[2 * k + 1]), "l"(acc1));
        }
        float a0, a1, b0, b1;
        asm("mov.b64 {%0, %1}, %2;" : "=f"(a0), "=f"(a1) : "l"(acc0));
        asm("mov.b64 {%0, %1}, %2;" : "=f"(b0), "=f"(b1) : "l"(acc1));
        spb[l * 33 + w] = (a0 + b0) + (a1 + b1);
        __syncthreads();  // bar A: all partials in sp

        // stage 2: warp w reduces its column; 4 partials/lane then 3 shfls;
        // lane 0 applies the activation (parallel across warps)
        {
            const float* spc = spb + w * 33 + jj;
            float s = (spc[0] + spc[8]) + (spc[16] + spc[24]);
            s += __shfl_xor_sync(0xffffffffu, s, 4);
            s += __shfl_xor_sync(0xffffffffu, s, 2);
            s += __shfl_xor_sync(0xffffffffu, s, 1);
            if (l == 0) {
                const float z = s + zxv;
                const int   q = w >> 3;
                if (q == 2) {               // g gate: tanh
                    const float zc = fminf(fmaxf(z, -15.f), 15.f);
                    const float ee = __expf(2.f * zc);
                    zs[w] = __fdividef(ee - 1.f, ee + 1.f);
                } else {                    // i,f,o gates: sigmoid
                    const float ee = __expf(-z);
                    zs[w] = __fdividef(1.f, 1.f + ee);
                }
            }
        }
        __syncthreads();  // bar B: activated gate values ready

        // final: warp 0, lanes 0..7 update cell and publish
        if (w == 0 && l < 8) {
            const float ig = zs[l],      fg = zs[8 + l];
            const float gg = zs[16 + l], og = zs[24 + l];
            const float c2 = fg * cst + ig * gg;
            cst = c2;
            const float cc = fminf(fmaxf(c2, -15.f), 15.f);
            const float ec = __expf(2.f * cc);
            const float h  = og * __fdividef(ec - 1.f, ec + 1.f);
            // publish FIRST: one coalesced 64B wavefront (8 lanes x 8B)
            unsigned long long pkw;
            asm("mov.b64 %0, {%1, %2};"
                : "=l"(pkw) : "f"(h), "r"((unsigned)(t + 1)));
            asm volatile("st.volatile.global.u64 [%0], %1;"
                         :: "l"(&g_hpk[(t + 1) & 1][u0 + l]), "l"(pkw)
                         : "memory");
            out[(size_t)t * U_HID + u0 + l] = h;    // off critical path
        }
        zxv = zxn;
        // no trailing barrier: zs(t+1) writes happen after bar A(t+1), which
        // warp 0 only reaches after gates; sp reuse is parity-buffered.
    }
}

// ============================================================================
extern "C" void kernel_launch(void* const* d_in, const int* in_sizes, int n_in,
                              void* d_out, int out_size) {
    const float* x    = (const float*)d_in[0];  // [1, 32768, 1024]
    const float* kw   = (const float*)d_in[1];  // [1024, 4096]
    const float* rw   = (const float*)d_in[2];  // [1024, 4096]
    const float* bias = (const float*)d_in[3];  // [4096]
    float* out = (float*)d_out;                 // [1, 32768, 1024]

    int sms = 148;
    cudaDeviceGetAttribute(&sms, cudaDevAttrMultiProcessorCount, 0);
    int nGemm = sms - N_LSTM_CTAS;              // producer CTAs on spare SMs
    if (nGemm < 1) nGemm = 1;

    init_state<<<1, 1024>>>();
    mega<<<N_LSTM_CTAS + nGemm, 1024>>>(x, kw, bias, rw, out, nGemm);
}